// round 4
// baseline (speedup 1.0000x reference)
#include <cuda_runtime.h>

// FMREDynamicDropout: out = x * bernoulli_mask(threefry2x32, keep_prob[c])
// x: [32, 384, 56, 56] fp32, feature_importance: [384] fp32
//
// JAX (threefry_partitionable) semantics, verified bit-exact in R2:
//   key(42) -> (0, 42); ks2 = 0 ^ 42 ^ 0x1BD11BDA = 0x1BD11BF0
//   per element i: hash counter words (0, i); bits[i] = o0 ^ o1
//   mask = bits < (ceil(keep[c] * 2^23) << 9)   (pure uint compare)
//
// R3 optimization: rotl(x, r) via IMAD.WIDE (x * 2^r -> {lo, hi} halves) moves
// the rotate from the saturated alu pipe (SHF) to the fma pipe; the following
// OR+XOR fuses into a single 3-input LOP3. Multipliers loaded from device
// memory so ptxas cannot strength-reduce the multiply back into shifts.

#define NCH   384
#define HW    3136u
#define NTOT  38535168u   // 32*384*56*56

__device__ unsigned g_thresh[NCH];   // pre-shifted: ceil(keep*2^23) << 9
__device__ unsigned g_mult[8] = {    // 2^r for r = 13,15,26,6,17,29,16,24
    1u << 13, 1u << 15, 1u << 26, 1u << 6,
    1u << 17, 1u << 29, 1u << 16, 1u << 24
};

// ---------------- prep: min/max over feature_importance, integer thresholds ----
__global__ void prep_kernel(const float* __restrict__ fi) {
    int t = threadIdx.x;            // 384 threads
    float v = fi[t];
    float mn = v, mx = v;
    #pragma unroll
    for (int o = 16; o > 0; o >>= 1) {
        mn = fminf(mn, __shfl_xor_sync(0xffffffffu, mn, o));
        mx = fmaxf(mx, __shfl_xor_sync(0xffffffffu, mx, o));
    }
    __shared__ float smn[12], smx[12];
    if ((t & 31) == 0) { smn[t >> 5] = mn; smx[t >> 5] = mx; }
    __syncthreads();
    if (t == 0) {
        float a = smn[0], b = smx[0];
        #pragma unroll
        for (int i = 1; i < 12; i++) { a = fminf(a, smn[i]); b = fmaxf(b, smx[i]); }
        smn[0] = a; smx[0] = b;
    }
    __syncthreads();
    float fmin = smn[0], fmax = smx[0];
    // match reference fp32 op ordering (no fma contraction)
    float scaled = __fdiv_rn(__fsub_rn(v, fmin), __fsub_rn(fmax, fmin));
    float rate   = __fadd_rn(0.1f, __fmul_rn(0.4f, __fsub_rn(1.0f, scaled)));
    float keep   = __fsub_rn(1.0f, rate);
    unsigned Tm = (unsigned)ceilf(__fmul_rn(keep, 8388608.0f));   // <= 0.9*2^23
    g_thresh[t] = Tm << 9;
}

// ---------------- threefry round: rotate via IMAD.WIDE + fused LOP3 ----------
__device__ __forceinline__ void tf_round_m(unsigned& x0, unsigned& x1, unsigned mult) {
    x0 += x1;                                             // IADD3 / IMAD (ptxas balances)
    unsigned long long w = (unsigned long long)x1 * mult; // IMAD.WIDE.U32 (fma pipe)
    x1 = (((unsigned)w) | ((unsigned)(w >> 32))) ^ x0;    // single LOP3: (lo|hi)^x0
}

// returns o0 ^ o1 for counter words (0, i), key (0, 42)
__device__ __forceinline__ unsigned tf_bits(unsigned i, const unsigned* M) {
    const unsigned ks1 = 42u, ks2 = 0x1BD11BF0u;
    unsigned x0 = 0u;            // 0 + ks0
    unsigned x1 = i + ks1;
    tf_round_m(x0, x1, M[0]); tf_round_m(x0, x1, M[1]);
    tf_round_m(x0, x1, M[2]); tf_round_m(x0, x1, M[3]);
    x0 += ks1; x1 += ks2 + 1u;
    tf_round_m(x0, x1, M[4]); tf_round_m(x0, x1, M[5]);
    tf_round_m(x0, x1, M[6]); tf_round_m(x0, x1, M[7]);
    x0 += ks2; x1 += 0u + 2u;
    tf_round_m(x0, x1, M[0]); tf_round_m(x0, x1, M[1]);
    tf_round_m(x0, x1, M[2]); tf_round_m(x0, x1, M[3]);
    x0 += 0u;  x1 += ks1 + 3u;
    tf_round_m(x0, x1, M[4]); tf_round_m(x0, x1, M[5]);
    tf_round_m(x0, x1, M[6]); tf_round_m(x0, x1, M[7]);
    x0 += ks1; x1 += ks2 + 4u;
    tf_round_m(x0, x1, M[0]); tf_round_m(x0, x1, M[1]);
    tf_round_m(x0, x1, M[2]); tf_round_m(x0, x1, M[3]);
    x0 += ks2; x1 += 5u;
    return x0 ^ x1;
}

// ---------------- main: 8 consecutive elements (two float4) per thread -------
__global__ void __launch_bounds__(256) drop_kernel(const float* __restrict__ x,
                                                   float* __restrict__ out) {
    // load rotation multipliers into registers (opaque to const-folding)
    unsigned M[8];
    #pragma unroll
    for (int k = 0; k < 8; k++) M[k] = g_mult[k];

    unsigned j = (blockIdx.x * 256u + threadIdx.x) * 8u;   // j < NTOT, 8 | HW
    unsigned T = g_thresh[(j / HW) % (unsigned)NCH];       // one channel per thread

    float4 a = *reinterpret_cast<const float4*>(x + j);
    float4 b = *reinterpret_cast<const float4*>(x + j + 4);

    unsigned m[8];
    #pragma unroll
    for (int k = 0; k < 8; k++)
        m[k] = tf_bits(j + (unsigned)k, M);

    float4 oa, ob;
    oa.x = (m[0] < T) ? a.x : 0.0f;
    oa.y = (m[1] < T) ? a.y : 0.0f;
    oa.z = (m[2] < T) ? a.z : 0.0f;
    oa.w = (m[3] < T) ? a.w : 0.0f;
    ob.x = (m[4] < T) ? b.x : 0.0f;
    ob.y = (m[5] < T) ? b.y : 0.0f;
    ob.z = (m[6] < T) ? b.z : 0.0f;
    ob.w = (m[7] < T) ? b.w : 0.0f;

    *reinterpret_cast<float4*>(out + j)     = oa;
    *reinterpret_cast<float4*>(out + j + 4) = ob;
}

extern "C" void kernel_launch(void* const* d_in, const int* in_sizes, int n_in,
                              void* d_out, int out_size) {
    const float* x  = (const float*)d_in[0];
    const float* fi = (const float*)d_in[1];
    if (n_in >= 2 && in_sizes[0] == NCH) {   // robust to input ordering
        x  = (const float*)d_in[1];
        fi = (const float*)d_in[0];
    }
    prep_kernel<<<1, NCH>>>(fi);
    // NTOT / 8 elems-per-thread / 256 threads = 18816 blocks, no remainder
    drop_kernel<<<18816, 256>>>(x, (float*)d_out);
}

// round 5
// speedup vs baseline: 1.1918x; 1.1918x over previous
#include <cuda_runtime.h>

// FMREDynamicDropout: out = x * bernoulli_mask(threefry2x32, keep_prob[c])
// x: [32, 384, 56, 56] fp32, feature_importance: [384] fp32
//
// JAX (threefry_partitionable) semantics, verified bit-exact in R2:
//   key(42) -> (0, 42); ks2 = 0 ^ 42 ^ 0x1BD11BDA = 0x1BD11BF0
//   per element i: hash counter words (0, i); bits[i] = o0 ^ o1
//   mask = bits < (ceil(keep[c] * 2^23) << 9)   (pure uint compare)
//
// R4: HYBRID rounds. R2 (all-SHF) capped by alu pipe (91.8%); R3 (all wide-mul)
// went latency-bound (issue 58.7%). Here half the rotations are SHF (alu),
// half are IMAD.WIDE+fused LOP3 (fma), balancing both pipes at ~0.5 instr/cyc
// while keeping same-pipe latency on half the rounds. launch_bounds(256,3)
// gives ptxas ~85 regs to interleave hash chains and hide cross-pipe RAW.

#define NCH   384
#define HW    3136u
#define NTOT  38535168u   // 32*384*56*56

__device__ unsigned g_thresh[NCH];   // pre-shifted: ceil(keep*2^23) << 9
__device__ unsigned g_multw[4] = {   // 2^r for the WIDE rounds: r = 15, 6, 29, 24
    1u << 15, 1u << 6, 1u << 29, 1u << 24
};

// ---------------- prep: min/max over feature_importance, integer thresholds ----
__global__ void prep_kernel(const float* __restrict__ fi) {
    int t = threadIdx.x;            // 384 threads
    float v = fi[t];
    float mn = v, mx = v;
    #pragma unroll
    for (int o = 16; o > 0; o >>= 1) {
        mn = fminf(mn, __shfl_xor_sync(0xffffffffu, mn, o));
        mx = fmaxf(mx, __shfl_xor_sync(0xffffffffu, mx, o));
    }
    __shared__ float smn[12], smx[12];
    if ((t & 31) == 0) { smn[t >> 5] = mn; smx[t >> 5] = mx; }
    __syncthreads();
    if (t == 0) {
        float a = smn[0], b = smx[0];
        #pragma unroll
        for (int i = 1; i < 12; i++) { a = fminf(a, smn[i]); b = fmaxf(b, smx[i]); }
        smn[0] = a; smx[0] = b;
    }
    __syncthreads();
    float fmin = smn[0], fmax = smx[0];
    // match reference fp32 op ordering (no fma contraction)
    float scaled = __fdiv_rn(__fsub_rn(v, fmin), __fsub_rn(fmax, fmin));
    float rate   = __fadd_rn(0.1f, __fmul_rn(0.4f, __fsub_rn(1.0f, scaled)));
    float keep   = __fsub_rn(1.0f, rate);
    unsigned Tm = (unsigned)ceilf(__fmul_rn(keep, 8388608.0f));   // <= 0.9*2^23
    g_thresh[t] = Tm << 9;
}

// ---------------- threefry rounds: SHF form (alu) and WIDE form (fma) --------
__device__ __forceinline__ void tf_round_s(unsigned& x0, unsigned& x1, int r) {
    x0 += x1;                                   // IADD3/IMAD (ptxas balances)
    x1 = __funnelshift_l(x1, x1, r) ^ x0;       // SHF (alu) + LOP3 (alu)
}
__device__ __forceinline__ void tf_round_w(unsigned& x0, unsigned& x1, unsigned mult) {
    x0 += x1;
    unsigned long long w = (unsigned long long)x1 * mult;   // IMAD.WIDE (fma)
    x1 = (((unsigned)w) | ((unsigned)(w >> 32))) ^ x0;      // single LOP3: (lo|hi)^x0
}

// group A rotations (13,15,26,6): SHF, WIDE(2^15), SHF, WIDE(2^6)
// group B rotations (17,29,16,24): SHF, WIDE(2^29), SHF, WIDE(2^24)
__device__ __forceinline__ void tf_groupA(unsigned& x0, unsigned& x1, const unsigned* M) {
    tf_round_s(x0, x1, 13); tf_round_w(x0, x1, M[0]);
    tf_round_s(x0, x1, 26); tf_round_w(x0, x1, M[1]);
}
__device__ __forceinline__ void tf_groupB(unsigned& x0, unsigned& x1, const unsigned* M) {
    tf_round_s(x0, x1, 17); tf_round_w(x0, x1, M[2]);
    tf_round_s(x0, x1, 16); tf_round_w(x0, x1, M[3]);
}

// returns o0 ^ o1 for counter words (0, i), key (0, 42)
__device__ __forceinline__ unsigned tf_bits(unsigned i, const unsigned* M) {
    const unsigned ks1 = 42u, ks2 = 0x1BD11BF0u;
    unsigned x0 = 0u;            // 0 + ks0
    unsigned x1 = i + ks1;
    tf_groupA(x0, x1, M);  x0 += ks1; x1 += ks2 + 1u;
    tf_groupB(x0, x1, M);  x0 += ks2; x1 += 2u;
    tf_groupA(x0, x1, M);  /* x0 += 0 */ x1 += ks1 + 3u;
    tf_groupB(x0, x1, M);  x0 += ks1; x1 += ks2 + 4u;
    tf_groupA(x0, x1, M);  x0 += ks2; x1 += 5u;
    return x0 ^ x1;
}

// ---------------- main: 8 consecutive elements (two float4) per thread -------
__global__ void __launch_bounds__(256, 3) drop_kernel(const float* __restrict__ x,
                                                      float* __restrict__ out) {
    // wide-round multipliers in registers (opaque to const-folding -> no SHF)
    unsigned M[4];
    #pragma unroll
    for (int k = 0; k < 4; k++) M[k] = g_multw[k];

    unsigned j = (blockIdx.x * 256u + threadIdx.x) * 8u;   // j < NTOT, 8 | HW
    unsigned T = g_thresh[(j / HW) % (unsigned)NCH];       // one channel per thread

    float4 a = *reinterpret_cast<const float4*>(x + j);
    float4 b = *reinterpret_cast<const float4*>(x + j + 4);

    unsigned m[8];
    #pragma unroll
    for (int k = 0; k < 8; k++)
        m[k] = tf_bits(j + (unsigned)k, M);

    float4 oa, ob;
    oa.x = (m[0] < T) ? a.x : 0.0f;
    oa.y = (m[1] < T) ? a.y : 0.0f;
    oa.z = (m[2] < T) ? a.z : 0.0f;
    oa.w = (m[3] < T) ? a.w : 0.0f;
    ob.x = (m[4] < T) ? b.x : 0.0f;
    ob.y = (m[5] < T) ? b.y : 0.0f;
    ob.z = (m[6] < T) ? b.z : 0.0f;
    ob.w = (m[7] < T) ? b.w : 0.0f;

    *reinterpret_cast<float4*>(out + j)     = oa;
    *reinterpret_cast<float4*>(out + j + 4) = ob;
}

extern "C" void kernel_launch(void* const* d_in, const int* in_sizes, int n_in,
                              void* d_out, int out_size) {
    const float* x  = (const float*)d_in[0];
    const float* fi = (const float*)d_in[1];
    if (n_in >= 2 && in_sizes[0] == NCH) {   // robust to input ordering
        x  = (const float*)d_in[1];
        fi = (const float*)d_in[0];
    }
    prep_kernel<<<1, NCH>>>(fi);
    // NTOT / 8 elems-per-thread / 256 threads = 18816 blocks, no remainder
    drop_kernel<<<18816, 256>>>(x, (float*)d_out);
}